// round 2
// baseline (speedup 1.0000x reference)
#include <cuda_runtime.h>
#include <cstdint>

#define THREADS 512
#define NWARPS  (THREADS / 32)
#define TOPN    64
#define CANDCAP 512

__device__ __forceinline__ uint32_t f2key(float x) {
    uint32_t u = __float_as_uint(x);
    return (u & 0x80000000u) ? ~u : (u | 0x80000000u);
}
__device__ __forceinline__ float key2f(uint32_t k) {
    uint32_t u = (k & 0x80000000u) ? (k & 0x7FFFFFFFu) : ~k;
    return __uint_as_float(u);
}
__device__ __forceinline__ unsigned long long umin64(unsigned long long a, unsigned long long b) {
    return a < b ? a : b;
}

// Per-element processing: online softmax accumulation + top-8 register list insert.
#define PROC(xv, iv, acc) do {                                                     \
    float _x = (xv);                                                               \
    if (_x > m) {                                                                  \
        float _r = __expf(m - _x);                                                 \
        a0 *= _r; a1 *= _r; a2 *= _r; a3 *= _r;                                    \
        m = _x; (acc) += 1.0f;                                                     \
    } else {                                                                       \
        (acc) += __expf(_x - m);                                                   \
    }                                                                              \
    uint32_t _u = __float_as_uint(_x);                                             \
    uint32_t _key = (_u & 0x80000000u) ? ~_u : (_u | 0x80000000u);                 \
    unsigned long long _k = ((unsigned long long)_key << 32)                       \
                          | (unsigned int)(~(unsigned int)(iv));                   \
    if (_k > cmin) {                                                               \
        if      (c[0] == cmin) c[0] = _k;                                          \
        else if (c[1] == cmin) c[1] = _k;                                          \
        else if (c[2] == cmin) c[2] = _k;                                          \
        else if (c[3] == cmin) c[3] = _k;                                          \
        else if (c[4] == cmin) c[4] = _k;                                          \
        else if (c[5] == cmin) c[5] = _k;                                          \
        else if (c[6] == cmin) c[6] = _k;                                          \
        else                   c[7] = _k;                                          \
        cmin = c[0];                                                               \
        cmin = umin64(cmin, c[1]); cmin = umin64(cmin, c[2]);                      \
        cmin = umin64(cmin, c[3]); cmin = umin64(cmin, c[4]);                      \
        cmin = umin64(cmin, c[5]); cmin = umin64(cmin, c[6]);                      \
        cmin = umin64(cmin, c[7]);                                                 \
    }                                                                              \
} while (0)

__global__ __launch_bounds__(THREADS, 1)
void sampler_kernel(const float* __restrict__ logits,
                    const int*   __restrict__ top_ks,
                    const float* __restrict__ top_ps,
                    const float* __restrict__ min_ps,
                    const float* __restrict__ uvec,
                    float* __restrict__ out,
                    int B, int V, int K)
{
    __shared__ float sWm[NWARPS], sWs[NWARPS];
    __shared__ int   sWc[NWARPS];
    __shared__ float sM, sS, sLogZ;
    __shared__ uint32_t sT;
    __shared__ int sN;
    __shared__ unsigned long long sCand[CANDCAP];
    __shared__ uint32_t sKey[TOPN];
    __shared__ int      sIdx[TOPN];

    const int tid  = threadIdx.x;
    const int row  = blockIdx.x;
    const int lane = tid & 31;
    const int wid  = tid >> 5;

    const float* rowp = logits + (long long)row * V;

    float m  = __int_as_float(0xff800000);  // -inf
    float a0 = 0.f, a1 = 0.f, a2 = 0.f, a3 = 0.f;
    unsigned long long c[8] = {0, 0, 0, 0, 0, 0, 0, 0};
    unsigned long long cmin = 0ull;

    // ---- Main fused HBM pass: online softmax + per-thread top-8 ----
    const int nvec = V >> 2;
    const float4* r4 = reinterpret_cast<const float4*>(rowp);
    for (int vi = tid; vi < nvec; vi += THREADS) {
        float4 x = r4[vi];
        int base = vi << 2;
        PROC(x.x, base + 0, a0);
        PROC(x.y, base + 1, a1);
        PROC(x.z, base + 2, a2);
        PROC(x.w, base + 3, a3);
    }
    for (int i = (nvec << 2) + tid; i < V; i += THREADS) {
        float x = rowp[i];
        PROC(x, i, a0);
    }

    float s = (a0 + a1) + (a2 + a3);

    // ---- Block combine (max, sumexp) ----
    #pragma unroll
    for (int off = 16; off; off >>= 1) {
        float mo = __shfl_down_sync(0xffffffffu, m, off);
        float so = __shfl_down_sync(0xffffffffu, s, off);
        float M2 = fmaxf(m, mo);
        s = s * __expf(m - M2) + so * __expf(mo - M2);
        m = M2;
    }
    if (lane == 0) { sWm[wid] = m; sWs[wid] = s; }
    __syncthreads();
    uint32_t t_lo = 0, t_hi = 0;   // live only on tid 0
    if (tid == 0) {
        float M = sWm[0], S = sWs[0];
        #pragma unroll
        for (int w = 1; w < NWARPS; w++) {
            float mo = sWm[w], so = sWs[w];
            float M2 = fmaxf(M, mo);
            S = S * __expf(M - M2) + so * __expf(mo - M2);
            M = M2;
        }
        sM = M; sS = S;
        sLogZ = M + logf(S);
        sN = 0;
        t_lo = 0;
        t_hi = f2key(M);           // answer (64th-largest key) is <= key(max)
    }
    __syncthreads();

    // ---- Binary search on 32-bit key for the 64th-largest value ----
    // Invariant: count(key >= t_lo) >= TOPN. Counts taken on registers only.
    for (int it = 0; it < 32; it++) {
        if (tid == 0) sT = t_lo + ((t_hi - t_lo + 1u) >> 1);
        __syncthreads();
        uint32_t T = sT;
        int cnt = 0;
        #pragma unroll
        for (int q = 0; q < 8; q++) cnt += ((uint32_t)(c[q] >> 32) >= T) ? 1 : 0;
        cnt = __reduce_add_sync(0xffffffffu, cnt);
        if (lane == 0) sWc[wid] = cnt;
        __syncthreads();
        if (tid == 0) {
            int tot = 0;
            #pragma unroll
            for (int w = 0; w < NWARPS; w++) tot += sWc[w];
            if (tot >= TOPN) t_lo = sT; else t_hi = sT - 1u;
        }
    }
    if (tid == 0) sT = t_lo;
    __syncthreads();
    uint32_t v64 = sT;

    // ---- Collect candidates >= v64 ----
    #pragma unroll
    for (int q = 0; q < 8; q++) {
        if ((uint32_t)(c[q] >> 32) >= v64) {
            int p = atomicAdd(&sN, 1);
            if (p < CANDCAP) sCand[p] = c[q];
        }
    }
    __syncthreads();
    int n = sN < CANDCAP ? sN : CANDCAP;

    // ---- Exact rank by 64-bit key (value desc, index asc on ties) ----
    if (tid < n) {
        unsigned long long mine = sCand[tid];
        int rnk = 0;
        for (int j = 0; j < n; j++) rnk += (sCand[j] > mine) ? 1 : 0;
        if (rnk < TOPN) {
            sKey[rnk] = (uint32_t)(mine >> 32);
            sIdx[rnk] = (int)(~(uint32_t)mine);
        }
    }
    __syncthreads();

    // ---- Top-K logprob outputs ----
    if (tid < K) {
        float l = key2f(sKey[tid]);
        out[B + (long long)row * K + tid] = l - sLogZ;
        out[B + (long long)B * K + (long long)row * K + tid] = (float)sIdx[tid];
    }

    // ---- Serial sampling epilogue (matches reference's prefix-cumsum semantics) ----
    if (tid == 0) {
        float M = sM, S = sS;
        int   topk = top_ks[row];
        float tp = top_ps[row];
        float mp = min_ps[row];
        float uu = uvec[row];

        float cum = 0.f, total = 0.f, thresh = 0.f;
        float masked[TOPN];
        #pragma unroll 1
        for (int j = 0; j < TOPN; j++) {
            float p = __expf(key2f(sKey[j]) - M) / S;
            bool keep = (j < topk) && (cum <= tp);   // cum here = cumsum - prob
            cum += p;
            if (j == 0) thresh = p * mp;             // masked[0] is always kept
            float mj = keep ? p : 0.f;
            if (mj < thresh) mj = 0.f;
            total += mj;
            masked[j] = mj;
        }
        float target = uu * total;
        float cdf = 0.f;
        int pos = 0;
        #pragma unroll 1
        for (int j = 0; j < TOPN; j++) {
            cdf += masked[j];
            pos += (cdf < target) ? 1 : 0;
        }
        if (pos > TOPN - 1) pos = TOPN - 1;
        out[row] = (float)sIdx[pos];
    }
}

extern "C" void kernel_launch(void* const* d_in, const int* in_sizes, int n_in,
                              void* d_out, int out_size) {
    const float* logits = (const float*)d_in[0];
    const int*   top_ks = (const int*)d_in[1];
    const float* top_ps = (const float*)d_in[2];
    const float* min_ps = (const float*)d_in[3];
    const float* u      = (const float*)d_in[4];

    int B = in_sizes[1];
    int V = in_sizes[0] / B;
    int K = (out_size - B) / (2 * B);

    sampler_kernel<<<B, THREADS>>>(logits, top_ks, top_ps, min_ps, u,
                                   (float*)d_out, B, V, K);
}

// round 6
// speedup vs baseline: 3.9561x; 3.9561x over previous
#include <cuda_runtime.h>
#include <cstdint>

#define THREADS 1024
#define NWARPS  (THREADS / 32)
#define TOPN    64
#define CANDCAP 2048

__device__ __forceinline__ uint32_t f2key(float x) {
    uint32_t u = __float_as_uint(x);
    return (u & 0x80000000u) ? ~u : (u | 0x80000000u);
}
__device__ __forceinline__ float key2f(uint32_t k) {
    uint32_t u = (k & 0x80000000u) ? (k & 0x7FFFFFFFu) : ~k;
    return __uint_as_float(u);
}

struct PassA {
    float a0, a1, a2, a3, tmax;
    __device__ __forceinline__ void init() {
        a0 = a1 = a2 = a3 = 0.f;
        tmax = -3.402823466e38f;
    }
    __device__ __forceinline__ void acc4(float4 x) {
        a0 += __expf(x.x); a1 += __expf(x.y);
        a2 += __expf(x.z); a3 += __expf(x.w);
        tmax = fmaxf(tmax, fmaxf(fmaxf(x.x, x.y), fmaxf(x.z, x.w)));
    }
};

__device__ __forceinline__ void chk1(float val, int idx, uint32_t T,
                                     int* sN, unsigned long long* sCand) {
    uint32_t k = f2key(val);
    if (k >= T) {
        int p = atomicAdd(sN, 1);
        if (p < CANDCAP)
            sCand[p] = ((unsigned long long)k << 32) | (uint32_t)(~(uint32_t)idx);
    }
}
__device__ __forceinline__ void chk4(float4 x, int base, uint32_t T,
                                     int* sN, unsigned long long* sCand) {
    chk1(x.x, base + 0, T, sN, sCand);
    chk1(x.y, base + 1, T, sN, sCand);
    chk1(x.z, base + 2, T, sN, sCand);
    chk1(x.w, base + 3, T, sN, sCand);
}

__global__ __launch_bounds__(THREADS, 1)
void sampler_kernel(const float* __restrict__ logits,
                    const int*   __restrict__ top_ks,
                    const float* __restrict__ top_ps,
                    const float* __restrict__ min_ps,
                    const float* __restrict__ uvec,
                    float* __restrict__ out,
                    int B, int V, int K)
{
    __shared__ float sWs[NWARPS];
    __shared__ float sW2[NWARPS];
    __shared__ float sS;
    __shared__ uint32_t sT;
    __shared__ int sN;
    __shared__ unsigned long long sCand[CANDCAP];
    __shared__ uint32_t sKey[TOPN];
    __shared__ int      sIdx[TOPN];

    const int tid  = threadIdx.x;
    const int lane = tid & 31;
    const int wid  = tid >> 5;
    const int row  = blockIdx.x;

    const float*  rowp = logits + (long long)row * V;
    const float4* r4   = reinterpret_cast<const float4*>(rowp);
    const int nvec = V >> 2;

    // ================= Pass A: DRAM stream — sum of exp + thread max =========
    PassA pa; pa.init();

    int vi = tid;
    for (; vi + 3 * THREADS < nvec; vi += 4 * THREADS) {
        float4 x0 = r4[vi];
        float4 x1 = r4[vi +     THREADS];
        float4 x2 = r4[vi + 2 * THREADS];
        float4 x3 = r4[vi + 3 * THREADS];
        pa.acc4(x0); pa.acc4(x1); pa.acc4(x2); pa.acc4(x3);
    }
    for (; vi < nvec; vi += THREADS) {
        pa.acc4(r4[vi]);
    }
    for (int i = (nvec << 2) + tid; i < V; i += THREADS) {
        float x = rowp[i];
        pa.a0 += __expf(x);
        pa.tmax = fmaxf(pa.tmax, x);
    }

    float s = (pa.a0 + pa.a1) + (pa.a2 + pa.a3);
    float tmax = pa.tmax;

    // ---- warp reduce sum ----
    #pragma unroll
    for (int off = 16; off; off >>= 1)
        s += __shfl_xor_sync(0xffffffffu, s, off);

    // ---- warp 2nd-largest thread-max (leader exclusion) ----
    float v = tmax;
    float wm1 = v;
    #pragma unroll
    for (int off = 16; off; off >>= 1)
        wm1 = fmaxf(wm1, __shfl_xor_sync(0xffffffffu, wm1, off));
    unsigned bal = __ballot_sync(0xffffffffu, v == wm1);
    if (lane == (__ffs(bal) - 1)) v = -3.402823466e38f;
    float wm2 = v;
    #pragma unroll
    for (int off = 16; off; off >>= 1)
        wm2 = fmaxf(wm2, __shfl_xor_sync(0xffffffffu, wm2, off));

    if (lane == 0) { sWs[wid] = s; sW2[wid] = wm2; }
    __syncthreads();

    if (tid == 0) {
        float S = 0.f;
        float tmin = 3.402823466e38f;
        #pragma unroll
        for (int w = 0; w < NWARPS; w++) {
            S += sWs[w];
            tmin = fminf(tmin, sW2[w]);
        }
        sS = S;
        sT = f2key(tmin);   // >= 64 elements have key >= sT (2 per warp x 32 warps)
        sN = 0;
    }
    __syncthreads();

    // ================= Pass B: L2 re-read — collect candidates >= T ==========
    const uint32_t T = sT;
    vi = tid;
    for (; vi + 3 * THREADS < nvec; vi += 4 * THREADS) {
        float4 x0 = r4[vi];
        float4 x1 = r4[vi +     THREADS];
        float4 x2 = r4[vi + 2 * THREADS];
        float4 x3 = r4[vi + 3 * THREADS];
        chk4(x0,  vi                 << 2, T, &sN, sCand);
        chk4(x1, (vi +     THREADS)  << 2, T, &sN, sCand);
        chk4(x2, (vi + 2 * THREADS)  << 2, T, &sN, sCand);
        chk4(x3, (vi + 3 * THREADS)  << 2, T, &sN, sCand);
    }
    for (; vi < nvec; vi += THREADS) {
        chk4(r4[vi], vi << 2, T, &sN, sCand);
    }
    for (int i = (nvec << 2) + tid; i < V; i += THREADS) {
        chk1(rowp[i], i, T, &sN, sCand);
    }
    __syncthreads();

    int n = sN;
    if (n > CANDCAP) n = CANDCAP;

    // ---- exact rank among candidates (value desc, index asc on ties) ----
    for (int i = tid; i < n; i += THREADS) {
        unsigned long long mine = sCand[i];
        int rnk = 0;
        for (int j = 0; j < n; j++) rnk += (sCand[j] > mine) ? 1 : 0;
        if (rnk < TOPN) {
            sKey[rnk] = (uint32_t)(mine >> 32);
            sIdx[rnk] = (int)(~(uint32_t)mine);
        }
    }
    __syncthreads();

    // ---- top-K logprob outputs ----
    const float S = sS;
    const float logZ = logf(S);
    if (tid < K) {
        float l = key2f(sKey[tid]);
        out[B + (long long)row * K + tid] = l - logZ;
        out[B + (long long)B * K + (long long)row * K + tid] = (float)sIdx[tid];
    }

    // ---- serial sampling epilogue (reference's prefix-cumsum semantics) ----
    if (tid == 0) {
        int   topk = top_ks[row];
        float tp = top_ps[row];
        float mp = min_ps[row];
        float uu = uvec[row];

        float cum = 0.f, total = 0.f, thresh = 0.f;
        float masked[TOPN];
        #pragma unroll 1
        for (int j = 0; j < TOPN; j++) {
            float p = __expf(key2f(sKey[j])) / S;
            bool keep = (j < topk) && (cum <= tp);   // cum = cumsum - prob (exclusive)
            cum += p;
            if (j == 0) thresh = p * mp;             // masked[0] always kept
            float mj = keep ? p : 0.f;
            if (mj < thresh) mj = 0.f;
            total += mj;
            masked[j] = mj;
        }
        float target = uu * total;
        float cdf = 0.f;
        int pos = 0;
        #pragma unroll 1
        for (int j = 0; j < TOPN; j++) {
            cdf += masked[j];
            pos += (cdf < target) ? 1 : 0;
        }
        if (pos > TOPN - 1) pos = TOPN - 1;
        out[row] = (float)sIdx[pos];
    }
}

extern "C" void kernel_launch(void* const* d_in, const int* in_sizes, int n_in,
                              void* d_out, int out_size) {
    const float* logits = (const float*)d_in[0];
    const int*   top_ks = (const int*)d_in[1];
    const float* top_ps = (const float*)d_in[2];
    const float* min_ps = (const float*)d_in[3];
    const float* u      = (const float*)d_in[4];

    int B = in_sizes[1];
    int V = in_sizes[0] / B;
    int K = (out_size - B) / (2 * B);

    sampler_kernel<<<B, THREADS>>>(logits, top_ks, top_ps, min_ps, u,
                                   (float*)d_out, B, V, K);
}